// round 1
// baseline (speedup 1.0000x reference)
#include <cuda_runtime.h>

// Problem constants
#define SS 512
#define BB 64
#define HH 1024
#define EE 512
#define VV 32000
#define TWOH 2048
#define KTOT 3584        // 2048 ctx + 512 emb + 1024 h0
#define G4 4096
#define NCHUNK 32        // S chunks of 16 rows
#define CROWS 16
#define NSPLIT 4
#define KSPLIT 896       // 3584 / 4

// ---------------- scratch (static device globals; no allocation) ----------
__device__ float g_hw[BB];
__device__ float g_eM[BB * NCHUNK];
__device__ float g_eL[BB * NCHUNK];
__device__ float g_ctx[(size_t)BB * NCHUNK * TWOH];   // 16 MB
__device__ float g_A[BB * KTOT];                      // assembled rnn input [ctx|emb|h0]
__device__ float g_gatesP[NSPLIT * BB * G4];          // k-split partial gates

typedef unsigned long long u64;

__device__ __forceinline__ u64 dup2(float v) {
    u64 r; asm("mov.b64 %0,{%1,%1};" : "=l"(r) : "f"(v)); return r;
}
__device__ __forceinline__ void fma2(u64 &d, u64 a, u64 b) {
    asm("fma.rn.f32x2 %0,%1,%2,%0;" : "+l"(d) : "l"(a), "l"(b));
}
__device__ __forceinline__ float2 unp2(u64 v) {
    float2 r; asm("mov.b64 {%0,%1},%2;" : "=f"(r.x), "=f"(r.y) : "l"(v)); return r;
}
__device__ __forceinline__ float sigm(float x) { return 1.f / (1.f + __expf(-x)); }

// ---------------- K0: hw[b] = h0[b,:] . W_energy[:H] ----------------------
__global__ void k_hw(const float* __restrict__ hidden, const float* __restrict__ Wen) {
    int b = blockIdx.x;
    int tid = threadIdx.x;           // 128 threads
    float p = 0.f;
    for (int k = tid; k < HH; k += 128)
        p += hidden[b * HH + k] * Wen[k];
    __shared__ float red[128];
    red[tid] = p;
    __syncthreads();
    for (int o = 64; o >= 32; o >>= 1) {
        if (tid < o) red[tid] += red[tid + o];
        __syncthreads();
    }
    if (tid < 32) {
        float v = red[tid];
        for (int o = 16; o; o >>= 1) v += __shfl_xor_sync(~0u, v, o);
        if (tid == 0) g_hw[b] = v;
    }
}

// ---------------- K1: fused energy + local softmax + partial context ------
// grid (32 chunks, 64 b), 256 threads, dyn smem = 16*2048 + 2048 floats
__global__ __launch_bounds__(256, 1)
void k_attn(const float* __restrict__ enc, const float* __restrict__ Wen,
            const float* __restrict__ be) {
    extern __shared__ float sm[];
    float* rows = sm;                 // [16][2048]
    float* we   = sm + CROWS * TWOH;  // [2048]
    __shared__ float sE[CROWS];

    const int chunk = blockIdx.x;
    const int b     = blockIdx.y;
    const int tid   = threadIdx.x;
    const int s0    = chunk * CROWS;

    // stage w_e (W_energy[H:]) and 16 encoder rows into smem (float4)
    for (int i = tid; i < TWOH / 4; i += 256)
        ((float4*)we)[i] = ((const float4*)(Wen + HH))[i];
    for (int i = tid; i < CROWS * (TWOH / 4); i += 256) {
        int r = i >> 9, c = i & 511;
        ((float4*)rows)[r * (TWOH / 4) + c] =
            ((const float4*)(enc + ((size_t)(s0 + r) * BB + b) * TWOH))[c];
    }
    __syncthreads();

    const int w = tid >> 5, lane = tid & 31;
    const float hwb = g_hw[b];
    const float bev = be[0];

    // energies: 8 warps x 2 rows
    for (int rr = 0; rr < 2; rr++) {
        int r = w * 2 + rr;
        float p = 0.f;
        const float* row = rows + r * TWOH;
        for (int j = lane; j < TWOH; j += 32) p += row[j] * we[j];
        for (int o = 16; o; o >>= 1) p += __shfl_xor_sync(~0u, p, o);
        if (lane == 0) sE[r] = fmaxf(p + hwb + bev, 0.f);
    }
    __syncthreads();

    float m = -1e30f;
#pragma unroll
    for (int i = 0; i < CROWS; i++) m = fmaxf(m, sE[i]);
    float pe[CROWS];
    float l = 0.f;
#pragma unroll
    for (int i = 0; i < CROWS; i++) { pe[i] = __expf(sE[i] - m); l += pe[i]; }

    // partial context from staged rows (second use of the same data)
    float* dst = g_ctx + ((size_t)b * NCHUNK + chunk) * TWOH;
    for (int d = tid; d < TWOH; d += 256) {
        float v = 0.f;
#pragma unroll
        for (int i = 0; i < CROWS; i++) v += pe[i] * rows[i * TWOH + d];
        dst[d] = v;
    }
    if (tid == 0) { g_eM[b * NCHUNK + chunk] = m; g_eL[b * NCHUNK + chunk] = l; }
}

// ---------------- K2: combine chunks + assemble A = [ctx|emb|h0] ----------
__global__ void k_combine(const float* __restrict__ emb_table,
                          const int* __restrict__ x,
                          const float* __restrict__ hidden) {
    int b = blockIdx.x;
    int tid = threadIdx.x;            // 256
    float mv[NCHUNK], sc[NCHUNK];
    float M = -1e30f;
#pragma unroll
    for (int i = 0; i < NCHUNK; i++) { mv[i] = g_eM[b * NCHUNK + i]; M = fmaxf(M, mv[i]); }
    float L = 0.f;
#pragma unroll
    for (int i = 0; i < NCHUNK; i++) { sc[i] = __expf(mv[i] - M); L += g_eL[b * NCHUNK + i] * sc[i]; }
    float inv = 1.f / L;

    for (int d = tid; d < TWOH; d += 256) {
        float v = 0.f;
#pragma unroll
        for (int i = 0; i < NCHUNK; i++)
            v += sc[i] * g_ctx[((size_t)b * NCHUNK + i) * TWOH + d];
        g_A[b * KTOT + d] = v * inv;
    }
    int xb = x[b];
    for (int j = tid; j < EE; j += 256)
        g_A[b * KTOT + TWOH + j] = emb_table[(size_t)xb * EE + j];
    for (int j = tid; j < HH; j += 256)
        g_A[b * KTOT + TWOH + EE + j] = hidden[b * HH + j];
}

// ---------------- K3: gates GEMM (64 x 4096, K=3584), k-split 4 -----------
// grid (64 n-tiles of 64, 4 k-splits), 256 threads
__global__ __launch_bounds__(256, 1)
void k_gates(const float* __restrict__ Wih, const float* __restrict__ Whh) {
    __shared__ float As[32][64];   // [kk][m]
    __shared__ float Ws[32][64];   // [kk][n]
    const int nbase = blockIdx.x * 64;
    const int split = blockIdx.y;
    const int tid = threadIdx.x, tx = tid & 31, ty = tid >> 5;
    const int kstart = split * KSPLIT, kend = kstart + KSPLIT;

    u64 acc[4][2];
#pragma unroll
    for (int i = 0; i < 4; i++) { acc[i][0] = 0ull; acc[i][1] = 0ull; }

    for (int k0 = kstart; k0 < kend; k0 += 32) {
        // A tile: 64 rows x 32, transpose into [kk][m]
        for (int i = 0; i < 2; i++) {
            int idx = tid + i * 256;              // 0..511 float4
            int m = idx >> 3, kq = (idx & 7) * 4;
            float4 v = *(const float4*)(g_A + m * KTOT + k0 + kq);
            As[kq + 0][m] = v.x; As[kq + 1][m] = v.y;
            As[kq + 2][m] = v.z; As[kq + 3][m] = v.w;
        }
        // W tile: 64 rows x 32 (choose W_ih / W_hh per chunk; 2560 % 32 == 0)
        for (int i = 0; i < 2; i++) {
            int idx = tid + i * 256;
            int n = idx >> 3, kq = (idx & 7) * 4;
            float4 v;
            if (k0 < 2560)
                v = *(const float4*)(Wih + (size_t)(nbase + n) * 2560 + k0 + kq);
            else
                v = *(const float4*)(Whh + (size_t)(nbase + n) * 1024 + (k0 - 2560) + kq);
            Ws[kq + 0][n] = v.x; Ws[kq + 1][n] = v.y;
            Ws[kq + 2][n] = v.z; Ws[kq + 3][n] = v.w;
        }
        __syncthreads();
#pragma unroll
        for (int kk = 0; kk < 32; kk++) {
            u64 a0 = *(const u64*)&As[kk][ty * 8 + 0];
            u64 a1 = *(const u64*)&As[kk][ty * 8 + 2];
            u64 a2 = *(const u64*)&As[kk][ty * 8 + 4];
            u64 a3 = *(const u64*)&As[kk][ty * 8 + 6];
            float2 wv = *(const float2*)&Ws[kk][tx * 2];
            u64 b0 = dup2(wv.x), b1 = dup2(wv.y);
            fma2(acc[0][0], a0, b0); fma2(acc[1][0], a1, b0);
            fma2(acc[2][0], a2, b0); fma2(acc[3][0], a3, b0);
            fma2(acc[0][1], a0, b1); fma2(acc[1][1], a1, b1);
            fma2(acc[2][1], a2, b1); fma2(acc[3][1], a3, b1);
        }
        __syncthreads();
    }
    float* outp = g_gatesP + (size_t)split * BB * G4;
#pragma unroll
    for (int i = 0; i < 4; i++) {
        int m = ty * 8 + i * 2;
#pragma unroll
        for (int j = 0; j < 2; j++) {
            int n = nbase + tx * 2 + j;
            float2 v = unp2(acc[i][j]);
            outp[(m + 0) * G4 + n] = v.x;
            outp[(m + 1) * G4 + n] = v.y;
        }
    }
}

// ---------------- K3b: LSTM elementwise -----------------------------------
__global__ void k_lstm(const float* __restrict__ b_ih, const float* __restrict__ b_hh,
                       const float* __restrict__ cell,
                       float* __restrict__ h1o, float* __restrict__ c1o) {
    int idx = blockIdx.x * blockDim.x + threadIdx.x;   // 64*1024
    int b = idx >> 10, j = idx & 1023;
    float gi = 0, gf = 0, gg = 0, go = 0;
#pragma unroll
    for (int s = 0; s < NSPLIT; s++) {
        const float* gp = g_gatesP + ((size_t)s * BB + b) * G4;
        gi += gp[j]; gf += gp[1024 + j]; gg += gp[2048 + j]; go += gp[3072 + j];
    }
    gi += b_ih[j]        + b_hh[j];
    gf += b_ih[1024 + j] + b_hh[1024 + j];
    gg += b_ih[2048 + j] + b_hh[2048 + j];
    go += b_ih[3072 + j] + b_hh[3072 + j];
    float c0 = cell[b * HH + j];
    float c1 = sigm(gf) * c0 + sigm(gi) * tanhf(gg);
    float h1 = sigm(go) * tanhf(c1);
    h1o[b * HH + j] = h1;
    c1o[b * HH + j] = c1;
}

// ---------------- K4: FC GEMM  pred = h1 @ W_fc^T + b_fc ------------------
// grid 125 blocks of N=256, 256 threads, K=1024
__global__ __launch_bounds__(256, 1)
void k_fc(const float* __restrict__ h1, const float* __restrict__ Wfc,
          const float* __restrict__ bfc, float* __restrict__ pred) {
    __shared__ float As[32][64];    // [kk][m]
    __shared__ float Ws[32][256];   // [kk][n]
    const int nbase = blockIdx.x * 256;
    const int tid = threadIdx.x, tx = tid & 31, ty = tid >> 5;

    u64 acc[4][8];
#pragma unroll
    for (int i = 0; i < 4; i++)
#pragma unroll
        for (int j = 0; j < 8; j++) acc[i][j] = 0ull;

    for (int k0 = 0; k0 < HH; k0 += 32) {
        for (int i = 0; i < 2; i++) {
            int idx = tid + i * 256;
            int m = idx >> 3, kq = (idx & 7) * 4;
            float4 v = *(const float4*)(h1 + m * HH + k0 + kq);
            As[kq + 0][m] = v.x; As[kq + 1][m] = v.y;
            As[kq + 2][m] = v.z; As[kq + 3][m] = v.w;
        }
        for (int i = 0; i < 8; i++) {
            int idx = tid + i * 256;                 // 0..2047 float4
            int n = idx >> 3, kq = (idx & 7) * 4;
            float4 v = *(const float4*)(Wfc + (size_t)(nbase + n) * HH + k0 + kq);
            Ws[kq + 0][n] = v.x; Ws[kq + 1][n] = v.y;
            Ws[kq + 2][n] = v.z; Ws[kq + 3][n] = v.w;
        }
        __syncthreads();
#pragma unroll
        for (int kk = 0; kk < 32; kk++) {
            u64 a0 = *(const u64*)&As[kk][ty * 8 + 0];
            u64 a1 = *(const u64*)&As[kk][ty * 8 + 2];
            u64 a2 = *(const u64*)&As[kk][ty * 8 + 4];
            u64 a3 = *(const u64*)&As[kk][ty * 8 + 6];
            float4 w0 = *(const float4*)&Ws[kk][tx * 8 + 0];
            float4 w1 = *(const float4*)&Ws[kk][tx * 8 + 4];
            u64 bb;
            bb = dup2(w0.x); fma2(acc[0][0], a0, bb); fma2(acc[1][0], a1, bb); fma2(acc[2][0], a2, bb); fma2(acc[3][0], a3, bb);
            bb = dup2(w0.y); fma2(acc[0][1], a0, bb); fma2(acc[1][1], a1, bb); fma2(acc[2][1], a2, bb); fma2(acc[3][1], a3, bb);
            bb = dup2(w0.z); fma2(acc[0][2], a0, bb); fma2(acc[1][2], a1, bb); fma2(acc[2][2], a2, bb); fma2(acc[3][2], a3, bb);
            bb = dup2(w0.w); fma2(acc[0][3], a0, bb); fma2(acc[1][3], a1, bb); fma2(acc[2][3], a2, bb); fma2(acc[3][3], a3, bb);
            bb = dup2(w1.x); fma2(acc[0][4], a0, bb); fma2(acc[1][4], a1, bb); fma2(acc[2][4], a2, bb); fma2(acc[3][4], a3, bb);
            bb = dup2(w1.y); fma2(acc[0][5], a0, bb); fma2(acc[1][5], a1, bb); fma2(acc[2][5], a2, bb); fma2(acc[3][5], a3, bb);
            bb = dup2(w1.z); fma2(acc[0][6], a0, bb); fma2(acc[1][6], a1, bb); fma2(acc[2][6], a2, bb); fma2(acc[3][6], a3, bb);
            bb = dup2(w1.w); fma2(acc[0][7], a0, bb); fma2(acc[1][7], a1, bb); fma2(acc[2][7], a2, bb); fma2(acc[3][7], a3, bb);
        }
        __syncthreads();
    }
    // epilogue: 8 consecutive n per thread -> 2 float4 stores per m
    float bias[8];
#pragma unroll
    for (int j = 0; j < 8; j++) bias[j] = bfc[nbase + tx * 8 + j];
#pragma unroll
    for (int i = 0; i < 4; i++) {
        int m0 = ty * 8 + i * 2;
        float o0[8], o1[8];
#pragma unroll
        for (int j = 0; j < 8; j++) {
            float2 v = unp2(acc[i][j]);
            o0[j] = v.x + bias[j];
            o1[j] = v.y + bias[j];
        }
        float* p0 = pred + (size_t)(m0 + 0) * VV + nbase + tx * 8;
        float* p1 = pred + (size_t)(m0 + 1) * VV + nbase + tx * 8;
        *(float4*)(p0 + 0) = make_float4(o0[0], o0[1], o0[2], o0[3]);
        *(float4*)(p0 + 4) = make_float4(o0[4], o0[5], o0[6], o0[7]);
        *(float4*)(p1 + 0) = make_float4(o1[0], o1[1], o1[2], o1[3]);
        *(float4*)(p1 + 4) = make_float4(o1[4], o1[5], o1[6], o1[7]);
    }
}

// ---------------- launch ---------------------------------------------------
extern "C" void kernel_launch(void* const* d_in, const int* in_sizes, int n_in,
                              void* d_out, int out_size) {
    const int*   x       = (const int*)  d_in[0];
    const float* enc     = (const float*)d_in[1];
    const float* hidden  = (const float*)d_in[2];
    const float* cell    = (const float*)d_in[3];
    const float* emb     = (const float*)d_in[4];
    const float* Wen     = (const float*)d_in[5];
    const float* be      = (const float*)d_in[6];
    const float* Wih     = (const float*)d_in[7];
    const float* Whh     = (const float*)d_in[8];
    const float* b_ih    = (const float*)d_in[9];
    const float* b_hh    = (const float*)d_in[10];
    const float* Wfc     = (const float*)d_in[11];
    const float* bfc     = (const float*)d_in[12];

    float* pred = (float*)d_out;
    float* h1o  = pred + (size_t)BB * VV;
    float* c1o  = h1o + (size_t)BB * HH;

    const int smem_attn = (CROWS * TWOH + TWOH) * sizeof(float);  // 139264
    cudaFuncSetAttribute(k_attn, cudaFuncAttributeMaxDynamicSharedMemorySize, smem_attn);

    k_hw<<<BB, 128>>>(hidden, Wen);
    k_attn<<<dim3(NCHUNK, BB), 256, smem_attn>>>(enc, Wen, be);
    k_combine<<<BB, 256>>>(emb, x, hidden);
    k_gates<<<dim3(G4 / 64, NSPLIT), 256>>>(Wih, Whh);
    k_lstm<<<(BB * HH) / 256, 256>>>(b_ih, b_hh, cell, h1o, c1o);
    k_fc<<<VV / 256, 256>>>(h1o, Wfc, bfc, pred);
}

// round 2
// speedup vs baseline: 1.2872x; 1.2872x over previous
#include <cuda_runtime.h>
#include <cstdint>

// Problem constants
#define SS 512
#define BB 64
#define HH 1024
#define EE 512
#define VV 32000
#define TWOH 2048
#define KTOT 3584        // 2048 ctx + 512 emb + 1024 h0
#define G4 4096
#define NCHUNK 32        // S chunks of 16 rows
#define CROWS 16
#define NSPLIT 8
#define KSPLIT 448       // 3584 / 8

// ---------------- scratch (static device globals; no allocation) ----------
__device__ float g_hw[BB];
__device__ float g_eM[BB * NCHUNK];
__device__ float g_eL[BB * NCHUNK];
__device__ float g_ctx[(size_t)BB * NCHUNK * TWOH];   // 16 MB
__device__ float g_A[BB * KTOT];                      // assembled rnn input [ctx|emb|h0]
__device__ float g_gatesP[NSPLIT * BB * G4];          // k-split partial gates

typedef unsigned long long u64;

__device__ __forceinline__ u64 dup2(float v) {
    u64 r; asm("mov.b64 %0,{%1,%1};" : "=l"(r) : "f"(v)); return r;
}
__device__ __forceinline__ void fma2(u64 &d, u64 a, u64 b) {
    asm("fma.rn.f32x2 %0,%1,%2,%0;" : "+l"(d) : "l"(a), "l"(b));
}
__device__ __forceinline__ float2 unp2(u64 v) {
    float2 r; asm("mov.b64 {%0,%1},%2;" : "=f"(r.x), "=f"(r.y) : "l"(v)); return r;
}
__device__ __forceinline__ float sigm(float x) { return 1.f / (1.f + __expf(-x)); }

__device__ __forceinline__ void cpa16(uint32_t s, const void* g) {
    asm volatile("cp.async.cg.shared.global [%0], [%1], 16;" :: "r"(s), "l"(g));
}
__device__ __forceinline__ void cpa_commit() {
    asm volatile("cp.async.commit_group;");
}
__device__ __forceinline__ void cpa_wait0() {
    asm volatile("cp.async.wait_group 0;");
}

// ---------------- K0: hw[b] = h0[b,:] . W_energy[:H] ----------------------
__global__ void k_hw(const float* __restrict__ hidden, const float* __restrict__ Wen) {
    int b = blockIdx.x;
    int tid = threadIdx.x;           // 128 threads
    float p = 0.f;
    for (int k = tid; k < HH; k += 128)
        p += hidden[b * HH + k] * Wen[k];
    __shared__ float red[128];
    red[tid] = p;
    __syncthreads();
    for (int o = 64; o >= 32; o >>= 1) {
        if (tid < o) red[tid] += red[tid + o];
        __syncthreads();
    }
    if (tid < 32) {
        float v = red[tid];
        for (int o = 16; o; o >>= 1) v += __shfl_xor_sync(~0u, v, o);
        if (tid == 0) g_hw[b] = v;
    }
}

// ---------------- K1: fused energy + local softmax + partial context ------
// grid (32 chunks, 64 b), 256 threads, dyn smem = 16*2048 + 2048 floats
__global__ __launch_bounds__(256, 1)
void k_attn(const float* __restrict__ enc, const float* __restrict__ Wen,
            const float* __restrict__ be) {
    extern __shared__ float sm[];
    float* rows = sm;                 // [16][2048]
    float* we   = sm + CROWS * TWOH;  // [2048]
    __shared__ float sE[CROWS];

    const int chunk = blockIdx.x;
    const int b     = blockIdx.y;
    const int tid   = threadIdx.x;
    const int s0    = chunk * CROWS;

    uint32_t s_rows = (uint32_t)__cvta_generic_to_shared(rows);
    uint32_t s_we   = (uint32_t)__cvta_generic_to_shared(we);

    // stage w_e (W_energy[H:]) and 16 encoder rows into smem via cp.async
    for (int i = tid; i < TWOH / 4; i += 256)
        cpa16(s_we + i * 16, (const float4*)(Wen + HH) + i);
    for (int i = tid; i < CROWS * (TWOH / 4); i += 256) {
        int r = i >> 9, c = i & 511;
        cpa16(s_rows + (r * (TWOH / 4) + c) * 16,
              (const float4*)(enc + ((size_t)(s0 + r) * BB + b) * TWOH) + c);
    }
    cpa_commit();
    cpa_wait0();
    __syncthreads();

    const int w = tid >> 5, lane = tid & 31;
    const float hwb = g_hw[b];
    const float bev = be[0];

    // energies: 8 warps x 2 rows
    for (int rr = 0; rr < 2; rr++) {
        int r = w * 2 + rr;
        float p = 0.f;
        const float* row = rows + r * TWOH;
        for (int j = lane; j < TWOH; j += 32) p += row[j] * we[j];
        for (int o = 16; o; o >>= 1) p += __shfl_xor_sync(~0u, p, o);
        if (lane == 0) sE[r] = fmaxf(p + hwb + bev, 0.f);
    }
    __syncthreads();

    float m = -1e30f;
#pragma unroll
    for (int i = 0; i < CROWS; i++) m = fmaxf(m, sE[i]);
    float pe[CROWS];
    float l = 0.f;
#pragma unroll
    for (int i = 0; i < CROWS; i++) { pe[i] = __expf(sE[i] - m); l += pe[i]; }

    // partial context from staged rows (second use of the same data)
    float* dst = g_ctx + ((size_t)b * NCHUNK + chunk) * TWOH;
    for (int d = tid; d < TWOH; d += 256) {
        float v = 0.f;
#pragma unroll
        for (int i = 0; i < CROWS; i++) v += pe[i] * rows[i * TWOH + d];
        dst[d] = v;
    }
    if (tid == 0) { g_eM[b * NCHUNK + chunk] = m; g_eL[b * NCHUNK + chunk] = l; }
}

// ---------------- K2: combine chunks + assemble A = [ctx|emb|h0] ----------
__global__ void k_combine(const float* __restrict__ emb_table,
                          const int* __restrict__ x,
                          const float* __restrict__ hidden) {
    int b = blockIdx.x;
    int tid = threadIdx.x;            // 256
    float mv[NCHUNK], sc[NCHUNK];
    float M = -1e30f;
#pragma unroll
    for (int i = 0; i < NCHUNK; i++) { mv[i] = g_eM[b * NCHUNK + i]; M = fmaxf(M, mv[i]); }
    float L = 0.f;
#pragma unroll
    for (int i = 0; i < NCHUNK; i++) { sc[i] = __expf(mv[i] - M); L += g_eL[b * NCHUNK + i] * sc[i]; }
    float inv = 1.f / L;

    for (int d = tid; d < TWOH; d += 256) {
        float v = 0.f;
#pragma unroll
        for (int i = 0; i < NCHUNK; i++)
            v += sc[i] * g_ctx[((size_t)b * NCHUNK + i) * TWOH + d];
        g_A[b * KTOT + d] = v * inv;
    }
    int xb = x[b];
    for (int j = tid; j < EE; j += 256)
        g_A[b * KTOT + TWOH + j] = emb_table[(size_t)xb * EE + j];
    for (int j = tid; j < HH; j += 256)
        g_A[b * KTOT + TWOH + EE + j] = hidden[b * HH + j];
}

// ---------------- K3: gates GEMM (64 x 4096, K=3584), k-split 8 -----------
// grid (64 n-tiles of 64, 8 k-splits), 256 threads, register double-buffer
__global__ __launch_bounds__(256, 2)
void k_gates(const float* __restrict__ Wih, const float* __restrict__ Whh) {
    __shared__ float As[32][68];   // [kk][m] padded
    __shared__ float Ws[32][68];   // [kk][n] padded
    const int nbase = blockIdx.x * 64;
    const int split = blockIdx.y;
    const int tid = threadIdx.x, tx = tid & 31, ty = tid >> 5;
    const int kstart = split * KSPLIT;
    const int NCH = KSPLIT / 32;   // 14

    // per-thread copy coordinates
    const int i0 = tid,        i1 = tid + 256;
    const int m0c = i0 >> 3,   kq0 = (i0 & 7) * 4;
    const int m1c = i1 >> 3,   kq1 = (i1 & 7) * 4;

    u64 acc[4][2];
#pragma unroll
    for (int i = 0; i < 4; i++) { acc[i][0] = 0ull; acc[i][1] = 0ull; }

    float4 pa0, pa1, pw0, pw1;
    // prefetch first chunk
    {
        int k0 = kstart;
        pa0 = *(const float4*)(g_A + m0c * KTOT + k0 + kq0);
        pa1 = *(const float4*)(g_A + m1c * KTOT + k0 + kq1);
        if (k0 < 2560) {
            pw0 = *(const float4*)(Wih + (size_t)(nbase + m0c) * 2560 + k0 + kq0);
            pw1 = *(const float4*)(Wih + (size_t)(nbase + m1c) * 2560 + k0 + kq1);
        } else {
            pw0 = *(const float4*)(Whh + (size_t)(nbase + m0c) * 1024 + (k0 - 2560) + kq0);
            pw1 = *(const float4*)(Whh + (size_t)(nbase + m1c) * 1024 + (k0 - 2560) + kq1);
        }
    }

    for (int c = 0; c < NCH; c++) {
        // store prefetched tile
        As[kq0 + 0][m0c] = pa0.x; As[kq0 + 1][m0c] = pa0.y;
        As[kq0 + 2][m0c] = pa0.z; As[kq0 + 3][m0c] = pa0.w;
        As[kq1 + 0][m1c] = pa1.x; As[kq1 + 1][m1c] = pa1.y;
        As[kq1 + 2][m1c] = pa1.z; As[kq1 + 3][m1c] = pa1.w;
        Ws[kq0 + 0][m0c] = pw0.x; Ws[kq0 + 1][m0c] = pw0.y;
        Ws[kq0 + 2][m0c] = pw0.z; Ws[kq0 + 3][m0c] = pw0.w;
        Ws[kq1 + 0][m1c] = pw1.x; Ws[kq1 + 1][m1c] = pw1.y;
        Ws[kq1 + 2][m1c] = pw1.z; Ws[kq1 + 3][m1c] = pw1.w;
        __syncthreads();

        // prefetch next chunk (overlaps with compute below)
        if (c + 1 < NCH) {
            int k0 = kstart + (c + 1) * 32;
            pa0 = *(const float4*)(g_A + m0c * KTOT + k0 + kq0);
            pa1 = *(const float4*)(g_A + m1c * KTOT + k0 + kq1);
            if (k0 < 2560) {
                pw0 = *(const float4*)(Wih + (size_t)(nbase + m0c) * 2560 + k0 + kq0);
                pw1 = *(const float4*)(Wih + (size_t)(nbase + m1c) * 2560 + k0 + kq1);
            } else {
                pw0 = *(const float4*)(Whh + (size_t)(nbase + m0c) * 1024 + (k0 - 2560) + kq0);
                pw1 = *(const float4*)(Whh + (size_t)(nbase + m1c) * 1024 + (k0 - 2560) + kq1);
            }
        }

#pragma unroll
        for (int kk = 0; kk < 32; kk++) {
            ulonglong2 p0 = *(const ulonglong2*)&As[kk][ty * 8];
            ulonglong2 p1 = *(const ulonglong2*)&As[kk][ty * 8 + 4];
            float2 wv = *(const float2*)&Ws[kk][tx * 2];
            u64 b0 = dup2(wv.x), b1 = dup2(wv.y);
            fma2(acc[0][0], p0.x, b0); fma2(acc[1][0], p0.y, b0);
            fma2(acc[2][0], p1.x, b0); fma2(acc[3][0], p1.y, b0);
            fma2(acc[0][1], p0.x, b1); fma2(acc[1][1], p0.y, b1);
            fma2(acc[2][1], p1.x, b1); fma2(acc[3][1], p1.y, b1);
        }
        __syncthreads();
    }
    float* outp = g_gatesP + (size_t)split * BB * G4;
#pragma unroll
    for (int i = 0; i < 4; i++) {
        int m = ty * 8 + i * 2;
#pragma unroll
        for (int j = 0; j < 2; j++) {
            int n = nbase + tx * 2 + j;
            float2 v = unp2(acc[i][j]);
            outp[(m + 0) * G4 + n] = v.x;
            outp[(m + 1) * G4 + n] = v.y;
        }
    }
}

// ---------------- K3b: LSTM elementwise -----------------------------------
__global__ void k_lstm(const float* __restrict__ b_ih, const float* __restrict__ b_hh,
                       const float* __restrict__ cell,
                       float* __restrict__ h1o, float* __restrict__ c1o) {
    int idx = blockIdx.x * blockDim.x + threadIdx.x;   // 64*1024
    int b = idx >> 10, j = idx & 1023;
    float gi = 0, gf = 0, gg = 0, go = 0;
#pragma unroll
    for (int s = 0; s < NSPLIT; s++) {
        const float* gp = g_gatesP + ((size_t)s * BB + b) * G4;
        gi += gp[j]; gf += gp[1024 + j]; gg += gp[2048 + j]; go += gp[3072 + j];
    }
    gi += b_ih[j]        + b_hh[j];
    gf += b_ih[1024 + j] + b_hh[1024 + j];
    gg += b_ih[2048 + j] + b_hh[2048 + j];
    go += b_ih[3072 + j] + b_hh[3072 + j];
    float c0 = cell[b * HH + j];
    float c1 = sigm(gf) * c0 + sigm(gi) * tanhf(gg);
    float h1 = sigm(go) * tanhf(c1);
    h1o[b * HH + j] = h1;
    c1o[b * HH + j] = c1;
}

// ---------------- K4: FC GEMM  pred = h1 @ W_fc^T + b_fc ------------------
// grid 250 blocks of N=128, 256 threads, K=1024, register double-buffer
__global__ __launch_bounds__(256, 2)
void k_fc(const float* __restrict__ h1, const float* __restrict__ Wfc,
          const float* __restrict__ bfc, float* __restrict__ pred) {
    __shared__ float As[32][68];    // [kk][m] padded
    __shared__ float Ws[32][132];   // [kk][n] padded
    const int nbase = blockIdx.x * 128;
    const int tid = threadIdx.x, tx = tid & 31, ty = tid >> 5;

    // copy coords: A tile 64x32 (512 float4 -> 2/thread), W tile 128x32 (1024 float4 -> 4/thread)
    const int am0 = tid >> 3,         akq0 = (tid & 7) * 4;
    const int am1 = (tid + 256) >> 3, akq1 = ((tid + 256) & 7) * 4;

    u64 acc[4][4];
#pragma unroll
    for (int i = 0; i < 4; i++)
#pragma unroll
        for (int j = 0; j < 4; j++) acc[i][j] = 0ull;

    float4 pa0, pa1, pw[4];
    {
        int k0 = 0;
        pa0 = *(const float4*)(h1 + am0 * HH + k0 + akq0);
        pa1 = *(const float4*)(h1 + am1 * HH + k0 + akq1);
#pragma unroll
        for (int i = 0; i < 4; i++) {
            int idx = tid + i * 256;
            int n = idx >> 3, kq = (idx & 7) * 4;
            pw[i] = *(const float4*)(Wfc + (size_t)(nbase + n) * HH + k0 + kq);
        }
    }

    for (int c = 0; c < 32; c++) {
        As[akq0 + 0][am0] = pa0.x; As[akq0 + 1][am0] = pa0.y;
        As[akq0 + 2][am0] = pa0.z; As[akq0 + 3][am0] = pa0.w;
        As[akq1 + 0][am1] = pa1.x; As[akq1 + 1][am1] = pa1.y;
        As[akq1 + 2][am1] = pa1.z; As[akq1 + 3][am1] = pa1.w;
#pragma unroll
        for (int i = 0; i < 4; i++) {
            int idx = tid + i * 256;
            int n = idx >> 3, kq = (idx & 7) * 4;
            Ws[kq + 0][n] = pw[i].x; Ws[kq + 1][n] = pw[i].y;
            Ws[kq + 2][n] = pw[i].z; Ws[kq + 3][n] = pw[i].w;
        }
        __syncthreads();

        if (c + 1 < 32) {
            int k0 = (c + 1) * 32;
            pa0 = *(const float4*)(h1 + am0 * HH + k0 + akq0);
            pa1 = *(const float4*)(h1 + am1 * HH + k0 + akq1);
#pragma unroll
            for (int i = 0; i < 4; i++) {
                int idx = tid + i * 256;
                int n = idx >> 3, kq = (idx & 7) * 4;
                pw[i] = *(const float4*)(Wfc + (size_t)(nbase + n) * HH + k0 + kq);
            }
        }

#pragma unroll
        for (int kk = 0; kk < 32; kk++) {
            ulonglong2 p0 = *(const ulonglong2*)&As[kk][ty * 8];
            ulonglong2 p1 = *(const ulonglong2*)&As[kk][ty * 8 + 4];
            float4 wv = *(const float4*)&Ws[kk][tx * 4];
            u64 bb;
            bb = dup2(wv.x); fma2(acc[0][0], p0.x, bb); fma2(acc[1][0], p0.y, bb); fma2(acc[2][0], p1.x, bb); fma2(acc[3][0], p1.y, bb);
            bb = dup2(wv.y); fma2(acc[0][1], p0.x, bb); fma2(acc[1][1], p0.y, bb); fma2(acc[2][1], p1.x, bb); fma2(acc[3][1], p1.y, bb);
            bb = dup2(wv.z); fma2(acc[0][2], p0.x, bb); fma2(acc[1][2], p0.y, bb); fma2(acc[2][2], p1.x, bb); fma2(acc[3][2], p1.y, bb);
            bb = dup2(wv.w); fma2(acc[0][3], p0.x, bb); fma2(acc[1][3], p0.y, bb); fma2(acc[2][3], p1.x, bb); fma2(acc[3][3], p1.y, bb);
        }
        __syncthreads();
    }

    float bias[4];
#pragma unroll
    for (int j = 0; j < 4; j++) bias[j] = bfc[nbase + tx * 4 + j];
#pragma unroll
    for (int i = 0; i < 4; i++) {
        int m0 = ty * 8 + i * 2;
        float o0[4], o1[4];
#pragma unroll
        for (int j = 0; j < 4; j++) {
            float2 v = unp2(acc[i][j]);
            o0[j] = v.x + bias[j];
            o1[j] = v.y + bias[j];
        }
        float* p0 = pred + (size_t)(m0 + 0) * VV + nbase + tx * 4;
        float* p1 = pred + (size_t)(m0 + 1) * VV + nbase + tx * 4;
        *(float4*)p0 = make_float4(o0[0], o0[1], o0[2], o0[3]);
        *(float4*)p1 = make_float4(o1[0], o1[1], o1[2], o1[3]);
    }
}

// ---------------- launch ---------------------------------------------------
extern "C" void kernel_launch(void* const* d_in, const int* in_sizes, int n_in,
                              void* d_out, int out_size) {
    const int*   x       = (const int*)  d_in[0];
    const float* enc     = (const float*)d_in[1];
    const float* hidden  = (const float*)d_in[2];
    const float* cell    = (const float*)d_in[3];
    const float* emb     = (const float*)d_in[4];
    const float* Wen     = (const float*)d_in[5];
    const float* be      = (const float*)d_in[6];
    const float* Wih     = (const float*)d_in[7];
    const float* Whh     = (const float*)d_in[8];
    const float* b_ih    = (const float*)d_in[9];
    const float* b_hh    = (const float*)d_in[10];
    const float* Wfc     = (const float*)d_in[11];
    const float* bfc     = (const float*)d_in[12];

    float* pred = (float*)d_out;
    float* h1o  = pred + (size_t)BB * VV;
    float* c1o  = h1o + (size_t)BB * HH;

    const int smem_attn = (CROWS * TWOH + TWOH) * sizeof(float);  // 139264
    cudaFuncSetAttribute(k_attn, cudaFuncAttributeMaxDynamicSharedMemorySize, smem_attn);

    k_hw<<<BB, 128>>>(hidden, Wen);
    k_attn<<<dim3(NCHUNK, BB), 256, smem_attn>>>(enc, Wen, be);
    k_combine<<<BB, 256>>>(emb, x, hidden);
    k_gates<<<dim3(G4 / 64, NSPLIT), 256>>>(Wih, Whh);
    k_lstm<<<(BB * HH) / 256, 256>>>(b_ih, b_hh, cell, h1o, c1o);
    k_fc<<<VV / 128, 256>>>(h1o, Wfc, bfc, pred);
}

// round 3
// speedup vs baseline: 1.3897x; 1.0796x over previous
#include <cuda_runtime.h>
#include <cstdint>

#define SS 512
#define BB 64
#define HH 1024
#define EE 512
#define VV 32000
#define TWOH 2048
#define KTOT 3584        // 2048 ctx + 512 emb + 1024 h0
#define G4 4096
#define NCHUNK 64        // S chunks of 8 rows
#define CROWS 8
#define NSPLIT 7
#define KSPLIT 512       // 3584 / 7 -> 16 chunks of 32

// ---------------- scratch ---------------------------------------------------
__device__ float g_hw[BB];
__device__ float g_eM[BB * NCHUNK];
__device__ float g_eL[BB * NCHUNK];
__device__ float g_ctx[(size_t)BB * NCHUNK * TWOH];   // 33.5 MB
__device__ float g_At[KTOT * BB];                     // A transposed [k][m]
__device__ float g_h1t[HH * BB];                      // h1 transposed [k][m]
__device__ float g_gatesP[NSPLIT * BB * G4];

typedef unsigned long long u64;

__device__ __forceinline__ u64 dup2(float v) {
    u64 r; asm("mov.b64 %0,{%1,%1};" : "=l"(r) : "f"(v)); return r;
}
__device__ __forceinline__ void fma2(u64 &d, u64 a, u64 b) {
    asm("fma.rn.f32x2 %0,%1,%2,%0;" : "+l"(d) : "l"(a), "l"(b));
}
__device__ __forceinline__ float2 unp2(u64 v) {
    float2 r; asm("mov.b64 {%0,%1},%2;" : "=f"(r.x), "=f"(r.y) : "l"(v)); return r;
}
__device__ __forceinline__ float sigm(float x) { return 1.f / (1.f + __expf(-x)); }

__device__ __forceinline__ void cpa16(uint32_t s, const void* g) {
    asm volatile("cp.async.cg.shared.global [%0], [%1], 16;" :: "r"(s), "l"(g));
}
__device__ __forceinline__ void cpa_commit() { asm volatile("cp.async.commit_group;"); }
__device__ __forceinline__ void cpa_wait0()  { asm volatile("cp.async.wait_group 0;"); }

// ---------------- K0: hw[b] = h0[b,:] . W_energy[:H] -----------------------
__global__ void k_hw(const float* __restrict__ hidden, const float* __restrict__ Wen) {
    int b = blockIdx.x;
    int tid = threadIdx.x;           // 128
    float p = 0.f;
    for (int k = tid; k < HH; k += 128)
        p += hidden[b * HH + k] * Wen[k];
    __shared__ float red[128];
    red[tid] = p;
    __syncthreads();
    for (int o = 64; o >= 32; o >>= 1) {
        if (tid < o) red[tid] += red[tid + o];
        __syncthreads();
    }
    if (tid < 32) {
        float v = red[tid];
        for (int o = 16; o; o >>= 1) v += __shfl_xor_sync(~0u, v, o);
        if (tid == 0) g_hw[b] = v;
    }
}

// ---------------- K1: energy + local softmax + partial context --------------
// grid (64 chunks, 64 b), 256 thr, dyn smem = (8*2048 + 2048)*4 = 72 KB -> 3 CTA/SM
__global__ __launch_bounds__(256)
void k_attn(const float* __restrict__ enc, const float* __restrict__ Wen,
            const float* __restrict__ be) {
    extern __shared__ float sm[];
    float* rows = sm;                 // [8][2048]
    float* we   = sm + CROWS * TWOH;  // [2048]
    __shared__ float sE[CROWS];

    const int chunk = blockIdx.x;
    const int b     = blockIdx.y;
    const int tid   = threadIdx.x;
    const int s0    = chunk * CROWS;

    uint32_t s_rows = (uint32_t)__cvta_generic_to_shared(rows);
    uint32_t s_we   = (uint32_t)__cvta_generic_to_shared(we);

    for (int i = tid; i < TWOH / 4; i += 256)
        cpa16(s_we + i * 16, (const float4*)(Wen + HH) + i);
    for (int i = tid; i < CROWS * (TWOH / 4); i += 256) {
        int r = i >> 9, c = i & 511;
        cpa16(s_rows + (r * (TWOH / 4) + c) * 16,
              (const float4*)(enc + ((size_t)(s0 + r) * BB + b) * TWOH) + c);
    }
    cpa_commit();
    cpa_wait0();
    __syncthreads();

    const int w = tid >> 5, lane = tid & 31;
    const float hwb = g_hw[b];
    const float bev = be[0];

    // 8 warps x 1 row
    {
        float p = 0.f;
        const float* row = rows + w * TWOH;
        for (int j = lane; j < TWOH; j += 32) p += row[j] * we[j];
        for (int o = 16; o; o >>= 1) p += __shfl_xor_sync(~0u, p, o);
        if (lane == 0) sE[w] = fmaxf(p + hwb + bev, 0.f);
    }
    __syncthreads();

    float m = -1e30f;
#pragma unroll
    for (int i = 0; i < CROWS; i++) m = fmaxf(m, sE[i]);
    float pe[CROWS];
    float l = 0.f;
#pragma unroll
    for (int i = 0; i < CROWS; i++) { pe[i] = __expf(sE[i] - m); l += pe[i]; }

    float* dst = g_ctx + ((size_t)b * NCHUNK + chunk) * TWOH;
    for (int d = tid; d < TWOH; d += 256) {
        float v = 0.f;
#pragma unroll
        for (int i = 0; i < CROWS; i++) v += pe[i] * rows[i * TWOH + d];
        dst[d] = v;
    }
    if (tid == 0) { g_eM[b * NCHUNK + chunk] = m; g_eL[b * NCHUNK + chunk] = l; }
}

// ---------------- K2: combine chunks + assemble At = [ctx|emb|h0]^T ---------
__global__ void k_combine(const float* __restrict__ emb_table,
                          const int* __restrict__ x,
                          const float* __restrict__ hidden) {
    int b = blockIdx.x;
    int tid = threadIdx.x;            // 256
    __shared__ float ssc[NCHUNK];
    __shared__ float sInv;
    if (tid == 0) {
        float M = -1e30f;
        for (int i = 0; i < NCHUNK; i++) M = fmaxf(M, g_eM[b * NCHUNK + i]);
        float L = 0.f;
        for (int i = 0; i < NCHUNK; i++) {
            float s = __expf(g_eM[b * NCHUNK + i] - M);
            ssc[i] = s;
            L += s * g_eL[b * NCHUNK + i];
        }
        sInv = 1.f / L;
    }
    __syncthreads();
    float inv = sInv;

    for (int d = tid; d < TWOH; d += 256) {
        float v = 0.f;
#pragma unroll 8
        for (int i = 0; i < NCHUNK; i++)
            v += ssc[i] * g_ctx[((size_t)b * NCHUNK + i) * TWOH + d];
        g_At[d * BB + b] = v * inv;
    }
    int xb = x[b];
    for (int j = tid; j < EE; j += 256)
        g_At[(TWOH + j) * BB + b] = emb_table[(size_t)xb * EE + j];
    for (int j = tid; j < HH; j += 256)
        g_At[(TWOH + EE + j) * BB + b] = hidden[b * HH + j];
}

// ============ shared GEMM core: 64m x 64n tile, thread = 8m x 2n ============
// As: [2][32][64]  (cp.async from transposed-A rows, broadcast reads)
// Ws: [2][32][68]  (LDG+STS transpose, conflict-free f2 reads)

// ---------------- K3: gates GEMM (64 x 4096, K=3584), ksplit 7 --------------
__global__ __launch_bounds__(256, 3)
void k_gates(const float* __restrict__ Wih, const float* __restrict__ Whh) {
    __shared__ float As[2][32][64];
    __shared__ float Ws[2][32][68];
    const int nbase = blockIdx.x * 64;
    const int split = blockIdx.y;
    const int tid = threadIdx.x, tx = tid & 31, ty = tid >> 5;
    const int kstart = split * KSPLIT;
    const int NCH = KSPLIT / 32;    // 16

    // W copy coords (2 float4 per thread over 64x32 tile)
    const int n0 = tid >> 3,          kq0 = (tid & 7) * 4;
    const int n1 = (tid + 256) >> 3,  kq1 = ((tid + 256) & 7) * 4;
    // A cp.async coords (2 x 16B per thread over 32x64)
    const int ak0 = tid >> 4,          aq0 = (tid & 15) * 4;
    const int ak1 = (tid + 256) >> 4,  aq1 = ((tid + 256) & 15) * 4;
    uint32_t sAs = (uint32_t)__cvta_generic_to_shared(&As[0][0][0]);

    u64 acc[4][2];
#pragma unroll
    for (int i = 0; i < 4; i++) { acc[i][0] = 0ull; acc[i][1] = 0ull; }

    float4 w0, w1;
    auto ldW = [&](int k0, float4& a, float4& b) {
        if (k0 < 2560) {
            a = *(const float4*)(Wih + (size_t)(nbase + n0) * 2560 + k0 + kq0);
            b = *(const float4*)(Wih + (size_t)(nbase + n1) * 2560 + k0 + kq1);
        } else {
            a = *(const float4*)(Whh + (size_t)(nbase + n0) * 1024 + (k0 - 2560) + kq0);
            b = *(const float4*)(Whh + (size_t)(nbase + n1) * 1024 + (k0 - 2560) + kq1);
        }
    };
    auto cpA = [&](int k0, int s) {
        cpa16(sAs + ((s * 32 + ak0) * 64 + aq0) * 4, g_At + (k0 + ak0) * BB + aq0);
        cpa16(sAs + ((s * 32 + ak1) * 64 + aq1) * 4, g_At + (k0 + ak1) * BB + aq1);
        cpa_commit();
    };
    auto stW = [&](int s, const float4& a, const float4& b) {
        Ws[s][kq0 + 0][n0] = a.x; Ws[s][kq0 + 1][n0] = a.y;
        Ws[s][kq0 + 2][n0] = a.z; Ws[s][kq0 + 3][n0] = a.w;
        Ws[s][kq1 + 0][n1] = b.x; Ws[s][kq1 + 1][n1] = b.y;
        Ws[s][kq1 + 2][n1] = b.z; Ws[s][kq1 + 3][n1] = b.w;
    };

    ldW(kstart, w0, w1);
    cpA(kstart, 0);
    stW(0, w0, w1);
    cpa_wait0();
    __syncthreads();

    for (int c = 0; c < NCH; c++) {
        int s = c & 1;
        if (c + 1 < NCH) {
            int k0 = kstart + (c + 1) * 32;
            ldW(k0, w0, w1);
            cpA(k0, s ^ 1);
        }
#pragma unroll
        for (int kk = 0; kk < 32; kk++) {
            ulonglong2 p0 = *(const ulonglong2*)&As[s][kk][ty * 8];
            ulonglong2 p1 = *(const ulonglong2*)&As[s][kk][ty * 8 + 4];
            float2 wv = *(const float2*)&Ws[s][kk][tx * 2];
            u64 b0 = dup2(wv.x), b1 = dup2(wv.y);
            fma2(acc[0][0], p0.x, b0); fma2(acc[1][0], p0.y, b0);
            fma2(acc[2][0], p1.x, b0); fma2(acc[3][0], p1.y, b0);
            fma2(acc[0][1], p0.x, b1); fma2(acc[1][1], p0.y, b1);
            fma2(acc[2][1], p1.x, b1); fma2(acc[3][1], p1.y, b1);
        }
        if (c + 1 < NCH) {
            stW(s ^ 1, w0, w1);
            cpa_wait0();
        }
        __syncthreads();
    }

    float* outp = g_gatesP + (size_t)split * BB * G4;
#pragma unroll
    for (int i = 0; i < 4; i++) {
        int m = ty * 8 + i * 2;
#pragma unroll
        for (int j = 0; j < 2; j++) {
            int n = nbase + tx * 2 + j;
            float2 v = unp2(acc[i][j]);
            outp[(m + 0) * G4 + n] = v.x;
            outp[(m + 1) * G4 + n] = v.y;
        }
    }
}

// ---------------- K3b: LSTM elementwise (also writes h1 transposed) --------
__global__ void k_lstm(const float* __restrict__ b_ih, const float* __restrict__ b_hh,
                       const float* __restrict__ cell,
                       float* __restrict__ h1o, float* __restrict__ c1o) {
    int idx = blockIdx.x * blockDim.x + threadIdx.x;   // 64*1024
    int b = idx >> 10, j = idx & 1023;
    float gi = 0, gf = 0, gg = 0, go = 0;
#pragma unroll
    for (int s = 0; s < NSPLIT; s++) {
        const float* gp = g_gatesP + ((size_t)s * BB + b) * G4;
        gi += gp[j]; gf += gp[1024 + j]; gg += gp[2048 + j]; go += gp[3072 + j];
    }
    gi += b_ih[j]        + b_hh[j];
    gf += b_ih[1024 + j] + b_hh[1024 + j];
    gg += b_ih[2048 + j] + b_hh[2048 + j];
    go += b_ih[3072 + j] + b_hh[3072 + j];
    float c0 = cell[b * HH + j];
    float c1 = sigm(gf) * c0 + sigm(gi) * tanhf(gg);
    float h1 = sigm(go) * tanhf(c1);
    h1o[b * HH + j] = h1;
    c1o[b * HH + j] = c1;
    g_h1t[j * BB + b] = h1;
}

// ---------------- K4: FC GEMM  pred = h1 @ W_fc^T + b_fc --------------------
// grid 500 CTAs of 64n, K=1024 (32 chunks)
__global__ __launch_bounds__(256, 3)
void k_fc(const float* __restrict__ Wfc, const float* __restrict__ bfc,
          float* __restrict__ pred) {
    __shared__ float As[2][32][64];
    __shared__ float Ws[2][32][68];
    const int nbase = blockIdx.x * 64;
    const int tid = threadIdx.x, tx = tid & 31, ty = tid >> 5;

    const int n0 = tid >> 3,          kq0 = (tid & 7) * 4;
    const int n1 = (tid + 256) >> 3,  kq1 = ((tid + 256) & 7) * 4;
    const int ak0 = tid >> 4,          aq0 = (tid & 15) * 4;
    const int ak1 = (tid + 256) >> 4,  aq1 = ((tid + 256) & 15) * 4;
    uint32_t sAs = (uint32_t)__cvta_generic_to_shared(&As[0][0][0]);

    u64 acc[4][2];
#pragma unroll
    for (int i = 0; i < 4; i++) { acc[i][0] = 0ull; acc[i][1] = 0ull; }

    float4 w0, w1;
    auto ldW = [&](int k0, float4& a, float4& b) {
        a = *(const float4*)(Wfc + (size_t)(nbase + n0) * HH + k0 + kq0);
        b = *(const float4*)(Wfc + (size_t)(nbase + n1) * HH + k0 + kq1);
    };
    auto cpA = [&](int k0, int s) {
        cpa16(sAs + ((s * 32 + ak0) * 64 + aq0) * 4, g_h1t + (k0 + ak0) * BB + aq0);
        cpa16(sAs + ((s * 32 + ak1) * 64 + aq1) * 4, g_h1t + (k0 + ak1) * BB + aq1);
        cpa_commit();
    };
    auto stW = [&](int s, const float4& a, const float4& b) {
        Ws[s][kq0 + 0][n0] = a.x; Ws[s][kq0 + 1][n0] = a.y;
        Ws[s][kq0 + 2][n0] = a.z; Ws[s][kq0 + 3][n0] = a.w;
        Ws[s][kq1 + 0][n1] = b.x; Ws[s][kq1 + 1][n1] = b.y;
        Ws[s][kq1 + 2][n1] = b.z; Ws[s][kq1 + 3][n1] = b.w;
    };

    ldW(0, w0, w1);
    cpA(0, 0);
    stW(0, w0, w1);
    cpa_wait0();
    __syncthreads();

    const int NCH = HH / 32;   // 32
    for (int c = 0; c < NCH; c++) {
        int s = c & 1;
        if (c + 1 < NCH) {
            int k0 = (c + 1) * 32;
            ldW(k0, w0, w1);
            cpA(k0, s ^ 1);
        }
#pragma unroll
        for (int kk = 0; kk < 32; kk++) {
            ulonglong2 p0 = *(const ulonglong2*)&As[s][kk][ty * 8];
            ulonglong2 p1 = *(const ulonglong2*)&As[s][kk][ty * 8 + 4];
            float2 wv = *(const float2*)&Ws[s][kk][tx * 2];
            u64 b0 = dup2(wv.x), b1 = dup2(wv.y);
            fma2(acc[0][0], p0.x, b0); fma2(acc[1][0], p0.y, b0);
            fma2(acc[2][0], p1.x, b0); fma2(acc[3][0], p1.y, b0);
            fma2(acc[0][1], p0.x, b1); fma2(acc[1][1], p0.y, b1);
            fma2(acc[2][1], p1.x, b1); fma2(acc[3][1], p1.y, b1);
        }
        if (c + 1 < NCH) {
            stW(s ^ 1, w0, w1);
            cpa_wait0();
        }
        __syncthreads();
    }

    float bias0 = bfc[nbase + tx * 2];
    float bias1 = bfc[nbase + tx * 2 + 1];
#pragma unroll
    for (int i = 0; i < 4; i++) {
        int m = ty * 8 + i * 2;
#pragma unroll
        for (int j = 0; j < 2; j++) {
            int n = nbase + tx * 2 + j;
            float bj = j ? bias1 : bias0;
            float2 v = unp2(acc[i][j]);
            pred[(size_t)(m + 0) * VV + n] = v.x + bj;
            pred[(size_t)(m + 1) * VV + n] = v.y + bj;
        }
    }
}

// ---------------- launch -----------------------------------------------------
extern "C" void kernel_launch(void* const* d_in, const int* in_sizes, int n_in,
                              void* d_out, int out_size) {
    const int*   x       = (const int*)  d_in[0];
    const float* enc     = (const float*)d_in[1];
    const float* hidden  = (const float*)d_in[2];
    const float* cell    = (const float*)d_in[3];
    const float* emb     = (const float*)d_in[4];
    const float* Wen     = (const float*)d_in[5];
    const float* be      = (const float*)d_in[6];
    const float* Wih     = (const float*)d_in[7];
    const float* Whh     = (const float*)d_in[8];
    const float* b_ih    = (const float*)d_in[9];
    const float* b_hh    = (const float*)d_in[10];
    const float* Wfc     = (const float*)d_in[11];
    const float* bfc     = (const float*)d_in[12];

    float* pred = (float*)d_out;
    float* h1o  = pred + (size_t)BB * VV;
    float* c1o  = h1o + (size_t)BB * HH;

    const int smem_attn = (CROWS * TWOH + TWOH) * sizeof(float);  // 73728
    cudaFuncSetAttribute(k_attn, cudaFuncAttributeMaxDynamicSharedMemorySize, smem_attn);

    k_hw<<<BB, 128>>>(hidden, Wen);
    k_attn<<<dim3(NCHUNK, BB), 256, smem_attn>>>(enc, Wen, be);
    k_combine<<<BB, 256>>>(emb, x, hidden);
    k_gates<<<dim3(G4 / 64, NSPLIT), 256>>>(Wih, Whh);
    k_lstm<<<(BB * HH) / 256, 256>>>(b_ih, b_hh, cell, h1o, c1o);
    k_fc<<<VV / 64, 256>>>(Wfc, bfc, pred);
}

// round 5
// speedup vs baseline: 1.9292x; 1.3882x over previous
#include <cuda_runtime.h>
#include <cstdint>

#define SS 512
#define BB 64
#define HH 1024
#define EE 512
#define VV 32000
#define TWOH 2048
#define KTOT 3584
#define G4 4096
#define NCHUNK 64
#define CROWS 8
#define NSPLIT 7
#define KSPLIT 512

// HMMA GEMM tile config
#define MT 128              // m rows per CTA (weight rows)
#define KC 32               // k per chunk
#define LDA 40              // bf16 row stride in smem (80B = 5 granules -> conflict-free)
#define OFF_AHI 0
#define OFF_ALO 10240       // 128*40*2
#define OFF_BHI 20480
#define OFF_BLO 25600       // + 64*40*2
#define STAGE 30720

// ---------------- scratch ----------------------------------------------------
__device__ float g_hw[BB];
__device__ float g_eM[BB * NCHUNK];
__device__ float g_eL[BB * NCHUNK];
__device__ float g_ctx[(size_t)BB * NCHUNK * TWOH];
__device__ unsigned short g_Bhi[BB * KTOT];   // rnn_in bf16 hi  [b][k]
__device__ unsigned short g_Blo[BB * KTOT];
__device__ unsigned short g_h1hi[BB * HH];
__device__ unsigned short g_h1lo[BB * HH];
__device__ float g_gatesP[NSPLIT * G4 * BB];  // [s][m][b]

__device__ __forceinline__ float sigm(float x) { return 1.f / (1.f + __expf(-x)); }

__device__ __forceinline__ void cpa16(uint32_t s, const void* g) {
    asm volatile("cp.async.cg.shared.global [%0], [%1], 16;" :: "r"(s), "l"(g));
}
__device__ __forceinline__ void cpa_commit() { asm volatile("cp.async.commit_group;"); }
__device__ __forceinline__ void cpa_wait0()  { asm volatile("cp.async.wait_group 0;"); }

__device__ __forceinline__ void ldsm4(uint32_t* r, uint32_t addr) {
    asm volatile("ldmatrix.sync.aligned.m8n8.x4.shared.b16 {%0,%1,%2,%3}, [%4];"
        : "=r"(r[0]), "=r"(r[1]), "=r"(r[2]), "=r"(r[3]) : "r"(addr));
}
__device__ __forceinline__ void mma16816(float* d, const uint32_t* a, const uint32_t* b) {
    asm volatile("mma.sync.aligned.m16n8k16.row.col.f32.bf16.bf16.f32 "
        "{%0,%1,%2,%3},{%4,%5,%6,%7},{%8,%9},{%0,%1,%2,%3};"
        : "+f"(d[0]), "+f"(d[1]), "+f"(d[2]), "+f"(d[3])
        : "r"(a[0]), "r"(a[1]), "r"(a[2]), "r"(a[3]), "r"(b[0]), "r"(b[1]));
}
__device__ __forceinline__ void st4(uint32_t a, uint32_t x, uint32_t y, uint32_t z, uint32_t w) {
    asm volatile("st.shared.v4.u32 [%0], {%1,%2,%3,%4};" :: "r"(a), "r"(x), "r"(y), "r"(z), "r"(w));
}

__device__ __forceinline__ void split16(float x, unsigned short& hi, unsigned short& lo) {
    uint32_t bx = __float_as_uint(x);
    hi = (unsigned short)(bx >> 16);
    float lf = x - __uint_as_float(bx & 0xFFFF0000u);
    lo = (unsigned short)(__float_as_uint(lf) >> 16);
}

// ---------------- K0 ----------------------------------------------------------
__global__ void k_hw(const float* __restrict__ hidden, const float* __restrict__ Wen) {
    int b = blockIdx.x, tid = threadIdx.x;
    float p = 0.f;
    for (int k = tid; k < HH; k += 128) p += hidden[b * HH + k] * Wen[k];
    __shared__ float red[128];
    red[tid] = p; __syncthreads();
    for (int o = 64; o >= 32; o >>= 1) { if (tid < o) red[tid] += red[tid + o]; __syncthreads(); }
    if (tid < 32) {
        float v = red[tid];
        for (int o = 16; o; o >>= 1) v += __shfl_xor_sync(~0u, v, o);
        if (tid == 0) g_hw[b] = v;
    }
}

// ---------------- K1: attention --------------------------------------------
__global__ __launch_bounds__(256)
void k_attn(const float* __restrict__ enc, const float* __restrict__ Wen,
            const float* __restrict__ be) {
    extern __shared__ float sm[];
    float* rows = sm;
    float* we   = sm + CROWS * TWOH;
    __shared__ float sE[CROWS];
    const int chunk = blockIdx.x, b = blockIdx.y, tid = threadIdx.x;
    const int s0 = chunk * CROWS;
    uint32_t s_rows = (uint32_t)__cvta_generic_to_shared(rows);
    uint32_t s_we   = (uint32_t)__cvta_generic_to_shared(we);

    for (int i = tid; i < TWOH / 4; i += 256)
        cpa16(s_we + i * 16, (const float4*)(Wen + HH) + i);
    for (int i = tid; i < CROWS * (TWOH / 4); i += 256) {
        int r = i >> 9, c = i & 511;
        cpa16(s_rows + (r * (TWOH / 4) + c) * 16,
              (const float4*)(enc + ((size_t)(s0 + r) * BB + b) * TWOH) + c);
    }
    cpa_commit(); cpa_wait0();
    __syncthreads();

    const int w = tid >> 5, lane = tid & 31;
    const float hwb = g_hw[b], bev = be[0];
    {
        float p = 0.f;
        const float* row = rows + w * TWOH;
        for (int j = lane; j < TWOH; j += 32) p += row[j] * we[j];
        for (int o = 16; o; o >>= 1) p += __shfl_xor_sync(~0u, p, o);
        if (lane == 0) sE[w] = fmaxf(p + hwb + bev, 0.f);
    }
    __syncthreads();
    float m = -1e30f;
#pragma unroll
    for (int i = 0; i < CROWS; i++) m = fmaxf(m, sE[i]);
    float pe[CROWS]; float l = 0.f;
#pragma unroll
    for (int i = 0; i < CROWS; i++) { pe[i] = __expf(sE[i] - m); l += pe[i]; }
    float* dst = g_ctx + ((size_t)b * NCHUNK + chunk) * TWOH;
    for (int d = tid; d < TWOH; d += 256) {
        float v = 0.f;
#pragma unroll
        for (int i = 0; i < CROWS; i++) v += pe[i] * rows[i * TWOH + d];
        dst[d] = v;
    }
    if (tid == 0) { g_eM[b * NCHUNK + chunk] = m; g_eL[b * NCHUNK + chunk] = l; }
}

// ---------------- K2: combine -> rnn_in split bf16 [b][k] -------------------
__global__ void k_combine(const float* __restrict__ emb_table,
                          const int* __restrict__ x,
                          const float* __restrict__ hidden) {
    int b = blockIdx.x, tid = threadIdx.x;
    __shared__ float ssc[NCHUNK];
    __shared__ float sInv;
    if (tid == 0) {
        float M = -1e30f;
        for (int i = 0; i < NCHUNK; i++) M = fmaxf(M, g_eM[b * NCHUNK + i]);
        float L = 0.f;
        for (int i = 0; i < NCHUNK; i++) {
            float s = __expf(g_eM[b * NCHUNK + i] - M);
            ssc[i] = s;
            L += s * g_eL[b * NCHUNK + i];
        }
        sInv = 1.f / L;
    }
    __syncthreads();
    float inv = sInv;
    unsigned short hi, lo;
    for (int d = tid; d < TWOH; d += 256) {
        float v = 0.f;
#pragma unroll 8
        for (int i = 0; i < NCHUNK; i++)
            v += ssc[i] * g_ctx[((size_t)b * NCHUNK + i) * TWOH + d];
        split16(v * inv, hi, lo);
        g_Bhi[b * KTOT + d] = hi; g_Blo[b * KTOT + d] = lo;
    }
    int xb = x[b];
    for (int j = tid; j < EE; j += 256) {
        split16(emb_table[(size_t)xb * EE + j], hi, lo);
        g_Bhi[b * KTOT + TWOH + j] = hi; g_Blo[b * KTOT + TWOH + j] = lo;
    }
    for (int j = tid; j < HH; j += 256) {
        split16(hidden[b * HH + j], hi, lo);
        g_Bhi[b * KTOT + TWOH + EE + j] = hi; g_Blo[b * KTOT + TWOH + EE + j] = lo;
    }
}

// ================= HMMA GEMM pieces ==========================================
// convert prefetched fp32 A regs -> bf16 hi/lo smem tiles
__device__ __forceinline__ void stsA_conv(uint32_t sb, const float4* pa, int cm, int ckq) {
    uint32_t h[8], lw[8];
#pragma unroll
    for (int i = 0; i < 4; i++) {
        uint32_t bx = __float_as_uint(pa[i].x), by = __float_as_uint(pa[i].y);
        uint32_t bz = __float_as_uint(pa[i].z), bw = __float_as_uint(pa[i].w);
        h[2 * i]     = __byte_perm(bx, by, 0x7632);
        h[2 * i + 1] = __byte_perm(bz, bw, 0x7632);
        float lx = pa[i].x - __uint_as_float(bx & 0xFFFF0000u);
        float ly = pa[i].y - __uint_as_float(by & 0xFFFF0000u);
        float lz = pa[i].z - __uint_as_float(bz & 0xFFFF0000u);
        float lv = pa[i].w - __uint_as_float(bw & 0xFFFF0000u);
        lw[2 * i]     = __byte_perm(__float_as_uint(lx), __float_as_uint(ly), 0x7632);
        lw[2 * i + 1] = __byte_perm(__float_as_uint(lz), __float_as_uint(lv), 0x7632);
    }
    uint32_t d = sb + OFF_AHI + cm * 80 + ckq * 2;
    st4(d, h[0], h[1], h[2], h[3]);
    st4(d + 16, h[4], h[5], h[6], h[7]);
    d = sb + OFF_ALO + cm * 80 + ckq * 2;
    st4(d, lw[0], lw[1], lw[2], lw[3]);
    st4(d + 16, lw[4], lw[5], lw[6], lw[7]);
}

// warp MMA over one staged chunk: acc[8][4], A 16m x 32k, B 64n x 32k
__device__ __forceinline__ void domma(uint32_t sb, float (*acc)[4], int w, int l) {
    const int arow = w * 16 + (l & 7) + ((l >> 3) & 1) * 8;
    const int acol = ((l >> 4) & 1) * 8;
    const int brof = ((l >> 4) & 1) * 8 + (l & 7);
    const int bcol = ((l >> 3) & 1) * 8;
#pragma unroll
    for (int ks = 0; ks < 2; ks++) {
        uint32_t ahi[4], alo[4];
        uint32_t ao = arow * 80 + (ks * 16 + acol) * 2;
        ldsm4(ahi, sb + OFF_AHI + ao);
        ldsm4(alo, sb + OFF_ALO + ao);
#pragma unroll
        for (int p = 0; p < 4; p++) {
            uint32_t bh[4], bl[4];
            uint32_t bo = (p * 16 + brof) * 80 + (ks * 16 + bcol) * 2;
            ldsm4(bh, sb + OFF_BHI + bo);
            ldsm4(bl, sb + OFF_BLO + bo);
            mma16816(acc[2 * p],     ahi, bh);
            mma16816(acc[2 * p + 1], ahi, bh + 2);
            mma16816(acc[2 * p],     alo, bh);
            mma16816(acc[2 * p + 1], alo, bh + 2);
            mma16816(acc[2 * p],     ahi, bl);
            mma16816(acc[2 * p + 1], ahi, bl + 2);
        }
    }
}

// ---------------- K3: gates GEMM  grid(32, 7) --------------------------------
__global__ __launch_bounds__(256, 2)
void k_gates_mm(const float* __restrict__ Wih, const float* __restrict__ Whh) {
    extern __shared__ char dsm[];
    uint32_t base = (uint32_t)__cvta_generic_to_shared(dsm);
    const int tid = threadIdx.x, w = tid >> 5, l = tid & 31;
    const int mbase = blockIdx.x * MT;
    const int split = blockIdx.y;
    const int kstart = split * KSPLIT;
    const int NCH = KSPLIT / KC;     // 16

    const int cm = tid >> 1, ckq = (tid & 1) * 16;
    const int bn = tid >> 2, bq = (tid & 3) * 16;

    float acc[8][4];
#pragma unroll
    for (int i = 0; i < 8; i++)
#pragma unroll
        for (int j = 0; j < 4; j++) acc[i][j] = 0.f;

    float4 pa[4];
    auto ldgA = [&](int kg) {
        const float* src = (kg < 2560)
            ? Wih + (size_t)(mbase + cm) * 2560 + kg
            : Whh + (size_t)(mbase + cm) * 1024 + (kg - 2560);
#pragma unroll
        for (int i = 0; i < 4; i++) pa[i] = *(const float4*)(src + ckq + i * 4);
    };
    auto cpaB = [&](int kg, uint32_t sb) {
        cpa16(sb + OFF_BHI + bn * 80 + bq, (const char*)g_Bhi + (size_t)bn * KTOT * 2 + kg * 2 + bq);
        cpa16(sb + OFF_BLO + bn * 80 + bq, (const char*)g_Blo + (size_t)bn * KTOT * 2 + kg * 2 + bq);
        cpa_commit();
    };

    ldgA(kstart);
    cpaB(kstart, base);
    for (int c = 0; c < NCH; c++) {
        uint32_t sb = base + (c & 1) * STAGE;
        stsA_conv(sb, pa, cm, ckq);
        cpa_wait0();
        __syncthreads();
        if (c + 1 < NCH) {
            int kg = kstart + (c + 1) * KC;
            ldgA(kg);
            cpaB(kg, base + ((c + 1) & 1) * STAGE);
        }
        domma(sb, acc, w, l);
        __syncthreads();
    }

    const int gid = l >> 2, tig = (l & 3) * 2;
    float* outp = g_gatesP + ((size_t)split * G4 + mbase + w * 16) * BB;
#pragma unroll
    for (int no = 0; no < 8; no++) {
        *(float2*)(outp + gid * BB + no * 8 + tig)       = make_float2(acc[no][0], acc[no][1]);
        *(float2*)(outp + (gid + 8) * BB + no * 8 + tig) = make_float2(acc[no][2], acc[no][3]);
    }
}

// ---------------- K3b: LSTM ---------------------------------------------------
__global__ void k_lstm(const float* __restrict__ b_ih, const float* __restrict__ b_hh,
                       const float* __restrict__ cell,
                       float* __restrict__ h1o, float* __restrict__ c1o) {
    int idx = blockIdx.x * blockDim.x + threadIdx.x;
    int b = idx & 63, j = idx >> 6;
    float gi = 0, gf = 0, gg = 0, go = 0;
#pragma unroll
    for (int s = 0; s < NSPLIT; s++) {
        const float* gp = g_gatesP + (size_t)s * G4 * BB;
        gi += gp[(j) * BB + b];
        gf += gp[(1024 + j) * BB + b];
        gg += gp[(2048 + j) * BB + b];
        go += gp[(3072 + j) * BB + b];
    }
    gi += b_ih[j]        + b_hh[j];
    gf += b_ih[1024 + j] + b_hh[1024 + j];
    gg += b_ih[2048 + j] + b_hh[2048 + j];
    go += b_ih[3072 + j] + b_hh[3072 + j];
    float c0 = cell[b * HH + j];
    float c1 = sigm(gf) * c0 + sigm(gi) * tanhf(gg);
    float h1 = sigm(go) * tanhf(c1);
    h1o[b * HH + j] = h1;
    c1o[b * HH + j] = c1;
    unsigned short hi, lo;
    split16(h1, hi, lo);
    g_h1hi[b * HH + j] = hi;
    g_h1lo[b * HH + j] = lo;
}

// ---------------- K4: FC GEMM  grid(250) --------------------------------------
__global__ __launch_bounds__(256, 2)
void k_fc_mm(const float* __restrict__ Wfc, const float* __restrict__ bfc,
             float* __restrict__ pred) {
    extern __shared__ char dsm[];
    uint32_t base = (uint32_t)__cvta_generic_to_shared(dsm);
    const int tid = threadIdx.x, w = tid >> 5, l = tid & 31;
    const int mbase = blockIdx.x * MT;
    const int NCH = HH / KC;         // 32

    const int cm = tid >> 1, ckq = (tid & 1) * 16;
    const int bn = tid >> 2, bq = (tid & 3) * 16;

    float acc[8][4];
#pragma unroll
    for (int i = 0; i < 8; i++)
#pragma unroll
        for (int j = 0; j < 4; j++) acc[i][j] = 0.f;

    float4 pa[4];
    auto ldgA = [&](int kg) {
        const float* src = Wfc + (size_t)(mbase + cm) * HH + kg;
#pragma unroll
        for (int i = 0; i < 4; i++) pa[i] = *(const float4*)(src + ckq + i * 4);
    };
    auto cpaB = [&](int kg, uint32_t sb) {
        cpa16(sb + OFF_BHI + bn * 80 + bq, (const char*)g_h1hi + (size_t)bn * HH * 2 + kg * 2 + bq);
        cpa16(sb + OFF_BLO + bn * 80 + bq, (const char*)g_h1lo + (size_t)bn * HH * 2 + kg * 2 + bq);
        cpa_commit();
    };

    ldgA(0);
    cpaB(0, base);
    for (int c = 0; c < NCH; c++) {
        uint32_t sb = base + (c & 1) * STAGE;
        stsA_conv(sb, pa, cm, ckq);
        cpa_wait0();
        __syncthreads();
        if (c + 1 < NCH) {
            int kg = (c + 1) * KC;
            ldgA(kg);
            cpaB(kg, base + ((c + 1) & 1) * STAGE);
        }
        domma(sb, acc, w, l);
        __syncthreads();
    }

    // epilogue: transpose through smem, add bias, coalesced store
    float* ts = (float*)dsm;      // [64][132]
    const int gid = l >> 2, tig = (l & 3) * 2;
    float bias0 = bfc[mbase + w * 16 + gid];
    float bias1 = bfc[mbase + w * 16 + gid + 8];
#pragma unroll
    for (int no = 0; no < 8; no++) {
        int n = no * 8 + tig;
        ts[n * 132 + w * 16 + gid]           = acc[no][0] + bias0;
        ts[(n + 1) * 132 + w * 16 + gid]     = acc[no][1] + bias0;
        ts[n * 132 + w * 16 + gid + 8]       = acc[no][2] + bias1;
        ts[(n + 1) * 132 + w * 16 + gid + 8] = acc[no][3] + bias1;
    }
    __syncthreads();
    {
        int b = tid >> 2, q = tid & 3;
        const float* srow = ts + b * 132 + q * 32;
        float* drow = pred + (size_t)b * VV + mbase + q * 32;
#pragma unroll
        for (int i = 0; i < 8; i++)
            *(float4*)(drow + i * 4) = make_float4(srow[i * 4], srow[i * 4 + 1],
                                                   srow[i * 4 + 2], srow[i * 4 + 3]);
    }
}

// ---------------- launch --------------------------------------------------------
extern "C" void kernel_launch(void* const* d_in, const int* in_sizes, int n_in,
                              void* d_out, int out_size) {
    const int*   x       = (const int*)  d_in[0];
    const float* enc     = (const float*)d_in[1];
    const float* hidden  = (const float*)d_in[2];
    const float* cell    = (const float*)d_in[3];
    const float* emb     = (const float*)d_in[4];
    const float* Wen     = (const float*)d_in[5];
    const float* be      = (const float*)d_in[6];
    const float* Wih     = (const float*)d_in[7];
    const float* Whh     = (const float*)d_in[8];
    const float* b_ih    = (const float*)d_in[9];
    const float* b_hh    = (const float*)d_in[10];
    const float* Wfc     = (const float*)d_in[11];
    const float* bfc     = (const float*)d_in[12];

    float* pred = (float*)d_out;
    float* h1o  = pred + (size_t)BB * VV;
    float* c1o  = h1o + (size_t)BB * HH;

    const int smem_attn = (CROWS * TWOH + TWOH) * sizeof(float);   // 72 KB
    const int smem_gemm = 2 * STAGE;                               // 61440
    cudaFuncSetAttribute(k_attn, cudaFuncAttributeMaxDynamicSharedMemorySize, smem_attn);
    cudaFuncSetAttribute(k_gates_mm, cudaFuncAttributeMaxDynamicSharedMemorySize, smem_gemm);
    cudaFuncSetAttribute(k_fc_mm, cudaFuncAttributeMaxDynamicSharedMemorySize, smem_gemm);

    k_hw<<<BB, 128>>>(hidden, Wen);
    k_attn<<<dim3(NCHUNK, BB), 256, smem_attn>>>(enc, Wen, be);
    k_combine<<<BB, 256>>>(emb, x, hidden);
    k_gates_mm<<<dim3(G4 / MT, NSPLIT), 256, smem_gemm>>>(Wih, Whh);
    k_lstm<<<(BB * HH) / 256, 256>>>(b_ih, b_hh, cell, h1o, c1o);
    k_fc_mm<<<VV / MT, 256, smem_gemm>>>(Wfc, bfc, pred);
}